// round 13
// baseline (speedup 1.0000x reference)
#include <cuda_runtime.h>

#define NI      1022      // interior size (N-2)
#define NF      1024      // full size N
#define PITCH   1056      // padded row pitch (33*128B rows)
#define XOFF    16        // field starts at col 16 -> loads at x-4 stay in-bounds
#define BATCH   8
#define ROWS    8         // output rows per thread (step-0 / gforce kernels)
#define TY      4         // thread rows per block (step-0 / gforce kernels)
#define RROWS   16        // output rows per thread (fused rolling kernel)
#define FTY2    4         // thread.y per block (fused rolling kernel)

// zero-initialized at context init; padding cols never written -> stay zero
__device__ float g_bufA[BATCH * NI * PITCH];
__device__ float g_bufB[BATCH * NI * PITCH];
__device__ float g_G[BATCH * NI * PITCH];     // G = force + conv(pad(force))
__device__ float g_coef[9];
__device__ float g_cf[1];

__constant__ float c_coef[9];

// --- fold mu/k1/k2/k3 into 10 scalars ---------------------------------------
__global__ void setup_coef_kernel(const float* __restrict__ mu,
                                  const float* __restrict__ k1,
                                  const float* __restrict__ k2,
                                  const float* __restrict__ k3) {
    float s3 = 0.0f;
    #pragma unroll
    for (int i = 0; i < 9; i++) s3 += k3[i];
    float inv = 1.0f / s3;
    #pragma unroll
    for (int i = 0; i < 9; i++) g_coef[i] = (k1[i] + k2[i]) * inv;
    const float Hval = 1.0f / (float)(NF - 1);
    g_cf[0] = Hval * Hval / (mu[0] * s3);
}

// --- G = force + conv(pad(force)), force = f_interior * cf -------------------
// Thread owns cols [x0,x0+4), rows [ybase, ybase+ROWS). Rolling over F rows.
__global__ void __launch_bounds__(32 * TY)
gforce_kernel(const float* __restrict__ f) {
    int lane  = threadIdx.x;
    int x0    = (blockIdx.x * 32 + lane) * 4;
    int ybase = (blockIdx.y * TY + threadIdx.y) * ROWS;
    int b     = blockIdx.z;
    if (ybase >= NI) return;

    float c0 = c_coef[0], c1 = c_coef[1], c2 = c_coef[2];
    float c3 = c_coef[3], c4 = c_coef[4], c5 = c_coef[5];
    float c6 = c_coef[6], c7 = c_coef[7], c8 = c_coef[8];
    const float cf = g_cf[0];

    float4 acc[ROWS];
    #pragma unroll
    for (int i = 0; i < ROWS; i++) { acc[i].x = acc[i].y = acc[i].z = acc[i].w = 0.f; }

    #pragma unroll
    for (int rj = 0; rj <= ROWS + 1; rj++) {
        int ri = rj - 1;
        int rr = ybase + ri;              // F row index
        if (rr < 0 || rr >= NI) continue;

        // F[rr][x0-1 .. x0+4] = cf * f[rr+1][x0 .. x0+5] (zero outside domain)
        const float* fr = f + ((size_t)b * NF + (rr + 1)) * NF;
        float4 qa = *(const float4*)(fr + x0);
        float4 qb = *(const float4*)(fr + x0 + 4);
        float e[6] = { qa.x, qa.y, qa.z, qa.w, qb.x, qb.y };
        float w[6];
        #pragma unroll
        for (int i = 0; i < 6; i++) {
            int cc = x0 - 1 + i;
            w[i] = ((unsigned)cc < (unsigned)NI) ? cf * e[i] : 0.f;
        }

        if (ri + 1 >= 0 && ri + 1 < ROWS) {       // top taps for row rr+1
            acc[ri + 1].x += c0 * w[0] + c1 * w[1] + c2 * w[2];
            acc[ri + 1].y += c0 * w[1] + c1 * w[2] + c2 * w[3];
            acc[ri + 1].z += c0 * w[2] + c1 * w[3] + c2 * w[4];
            acc[ri + 1].w += c0 * w[3] + c1 * w[4] + c2 * w[5];
        }
        if (ri >= 0 && ri < ROWS) {               // mid taps + center self term
            acc[ri].x += c3 * w[0] + c4 * w[1] + c5 * w[2] + w[1];
            acc[ri].y += c3 * w[1] + c4 * w[2] + c5 * w[3] + w[2];
            acc[ri].z += c3 * w[2] + c4 * w[3] + c5 * w[4] + w[3];
            acc[ri].w += c3 * w[3] + c4 * w[4] + c5 * w[5] + w[4];
        }
        if (ri - 1 >= 0 && ri - 1 < ROWS) {       // bottom taps for row rr-1
            acc[ri - 1].x += c6 * w[0] + c7 * w[1] + c8 * w[2];
            acc[ri - 1].y += c6 * w[1] + c7 * w[2] + c8 * w[3];
            acc[ri - 1].z += c6 * w[2] + c7 * w[3] + c8 * w[4];
            acc[ri - 1].w += c6 * w[3] + c7 * w[4] + c8 * w[5];
        }
    }

    #pragma unroll
    for (int i = 0; i < ROWS; i++) {
        int row = ybase + i;
        if (row >= NI) continue;
        float* grow = g_G + ((size_t)b * NI + row) * PITCH + XOFF;
        if (x0 + 3 < NI) {
            *(float4*)(grow + x0) = acc[i];
        } else {
            if (x0 + 0 < NI) grow[x0 + 0] = acc[i].x;
            if (x0 + 1 < NI) grow[x0 + 1] = acc[i].y;
        }
    }
}

// --- step 0: bufA = force + conv(hard_encode(pre)), force from f inline ------
__global__ void __launch_bounds__(32 * TY)
step0_kernel(const float* __restrict__ pre,
             const float* __restrict__ f,
             float* __restrict__ out) {
    const unsigned FULL = 0xffffffffu;
    int lane  = threadIdx.x;
    int x0    = (blockIdx.x * 32 + lane) * 4;
    int ybase = (blockIdx.y * TY + threadIdx.y) * ROWS;
    int b     = blockIdx.z;

    float c0 = c_coef[0], c1 = c_coef[1], c2 = c_coef[2];
    float c3 = c_coef[3], c4 = c_coef[4], c5 = c_coef[5];
    float c6 = c_coef[6], c7 = c_coef[7], c8 = c_coef[8];
    const float cf = g_cf[0];

    const float* src = pre + (size_t)b * NI * NI;
    const bool L31 = (lane == 31);

    float4 acc[ROWS];
    #pragma unroll
    for (int i = 0; i < ROWS; i++) {
        int row = ybase + i;
        if (row < NI) {
            const float* fp = f + ((size_t)b * NF + (row + 1)) * NF;
            float4 q = *(const float4*)(fp + x0);
            float t4 = __shfl_down_sync(FULL, q.x, 1);
            if (L31) t4 = (x0 + 4 < NF) ? fp[x0 + 4] : 0.0f;
            acc[i].x = q.y * cf; acc[i].y = q.z * cf;
            acc[i].z = q.w * cf; acc[i].w = t4 * cf;
        } else {
            acc[i].x = acc[i].y = acc[i].z = acc[i].w = 0.0f;
        }
    }

    #pragma unroll
    for (int rj = 0; rj <= ROWS + 1; rj++) {
        int ri  = rj - 1;
        int row = ybase + ri;
        if (row < 0 || row >= NI) continue;

        const float* rp = src + (size_t)row * NI;
        float l, rr; float4 v;
        l   = (x0 - 1 >= 0 && x0 - 1 < NI) ? rp[x0 - 1] : 0.0f;
        v.x = (x0 + 0 < NI) ? rp[x0 + 0] : 0.0f;
        v.y = (x0 + 1 < NI) ? rp[x0 + 1] : 0.0f;
        v.z = (x0 + 2 < NI) ? rp[x0 + 2] : 0.0f;
        v.w = (x0 + 3 < NI) ? rp[x0 + 3] : 0.0f;
        rr  = (x0 + 4 < NI) ? rp[x0 + 4] : 0.0f;

        if (ri + 1 >= 0 && ri + 1 < ROWS) {
            acc[ri + 1].x += c0 * l   + c1 * v.x + c2 * v.y;
            acc[ri + 1].y += c0 * v.x + c1 * v.y + c2 * v.z;
            acc[ri + 1].z += c0 * v.y + c1 * v.z + c2 * v.w;
            acc[ri + 1].w += c0 * v.z + c1 * v.w + c2 * rr;
        }
        if (ri >= 0 && ri < ROWS) {
            acc[ri].x += c3 * l   + c4 * v.x + c5 * v.y;
            acc[ri].y += c3 * v.x + c4 * v.y + c5 * v.z;
            acc[ri].z += c3 * v.y + c4 * v.z + c5 * v.w;
            acc[ri].w += c3 * v.z + c4 * v.w + c5 * rr;
        }
        if (ri - 1 >= 0 && ri - 1 < ROWS) {
            acc[ri - 1].x += c6 * l   + c7 * v.x + c8 * v.y;
            acc[ri - 1].y += c6 * v.x + c7 * v.y + c8 * v.z;
            acc[ri - 1].z += c6 * v.y + c7 * v.z + c8 * v.w;
            acc[ri - 1].w += c6 * v.z + c7 * v.w + c8 * rr;
        }
    }

    #pragma unroll
    for (int i = 0; i < ROWS; i++) {
        int row = ybase + i;
        if (row >= NI) continue;
        float* orow = out + ((size_t)b * NI + row) * PITCH + XOFF;
        if (x0 + 3 < NI) {
            *(float4*)(orow + x0) = acc[i];
        } else {
            if (x0 + 0 < NI) orow[x0 + 0] = acc[i].x;
            if (x0 + 1 < NI) orow[x0 + 1] = acc[i].y;
        }
    }
}

// --- fused 2-step Jacobi: mid = conv(in); out = G + conv(mid) -----------------
// Thread owns cols [x0, x0+4) and output rows [ybase, ybase+RROWS).
// 4 loads/iteration: 3x float4 input window + 1x float4 G (aligned, no halo).
template<bool COMPACT_OUT>
__global__ void __launch_bounds__(32 * FTY2)
fused2r_kernel(const float* __restrict__ in,
               float* __restrict__ out, int out_pitch) {
    const int lane  = threadIdx.x;
    const int x0    = (blockIdx.x * 32 + lane) * 4;
    const int ybase = (blockIdx.y * FTY2 + threadIdx.y) * RROWS;
    const int b     = blockIdx.z;

    const float c0 = c_coef[0], c1 = c_coef[1], c2 = c_coef[2];
    const float c3 = c_coef[3], c4 = c_coef[4], c5 = c_coef[5];
    const float c6 = c_coef[6], c7 = c_coef[7], c8 = c_coef[8];

    const float* src = in     + (size_t)b * NI * PITCH + XOFF;
    const float* gsc = g_G    + (size_t)b * NI * PITCH + XOFF;
    float*       dst = out    + (size_t)b * NI * out_pitch;

    float inA[8], inB[8], inC[8];   // input rows r-2, r-1, r (cols x0-2..x0+5)
    float mA[6],  mB[6],  mC[6];    // mid rows r-3, r-2, r-1 (cols x0-1..x0+4)

    #pragma unroll
    for (int i = 0; i < 8; i++) { inA[i] = 0.f; inB[i] = 0.f; inC[i] = 0.f; }
    #pragma unroll
    for (int i = 0; i < 6; i++) { mA[i] = 0.f; mB[i] = 0.f; mC[i] = 0.f; }

    const float* rp = src + (size_t)(ybase - 2) * PITCH;

    for (int it = 0; it < RROWS + 4; it++) {
        const int r = ybase - 2 + it;

        // ---- shift input window, load row r (3 aligned float4) ---------------
        #pragma unroll
        for (int i = 0; i < 8; i++) { inA[i] = inB[i]; inB[i] = inC[i]; }
        if ((unsigned)r < (unsigned)NI) {
            float4 qa = *(const float4*)(rp + x0 - 4);
            float4 qb = *(const float4*)(rp + x0);
            float4 qc = *(const float4*)(rp + x0 + 4);
            inC[0] = qa.z; inC[1] = qa.w;
            inC[2] = qb.x; inC[3] = qb.y; inC[4] = qb.z; inC[5] = qb.w;
            inC[6] = qc.x; inC[7] = qc.y;
        } else {
            #pragma unroll
            for (int i = 0; i < 8; i++) inC[i] = 0.f;
        }
        rp += PITCH;

        // ---- shift mid window, compute mid row rm = r-1 (pure conv) ----------
        #pragma unroll
        for (int i = 0; i < 6; i++) { mA[i] = mB[i]; mB[i] = mC[i]; }

        const int rm = r - 1;
        if ((unsigned)rm < (unsigned)NI) {
            #pragma unroll
            for (int i = 0; i < 6; i++) {
                int gc = x0 - 1 + i;
                float vmid =
                      c0 * inA[i] + c1 * inA[i + 1] + c2 * inA[i + 2]
                    + c3 * inB[i] + c4 * inB[i + 1] + c5 * inB[i + 2]
                    + c6 * inC[i] + c7 * inC[i + 1] + c8 * inC[i + 2];
                mC[i] = ((unsigned)gc < (unsigned)NI) ? vmid : 0.f;
            }
        } else {
            #pragma unroll
            for (int i = 0; i < 6; i++) mC[i] = 0.f;
        }

        // ---- output row ro = r-2: out = G + conv(mid) ------------------------
        const int ro = r - 2;
        if (ro >= ybase && ro < NI) {
            float4 g4 = *(const float4*)(gsc + (size_t)ro * PITCH + x0);
            float o[4];
            #pragma unroll
            for (int j = 0; j < 4; j++) {
                o[j] = c0 * mA[j] + c1 * mA[j + 1] + c2 * mA[j + 2]
                     + c3 * mB[j] + c4 * mB[j + 1] + c5 * mB[j + 2]
                     + c6 * mC[j] + c7 * mC[j + 1] + c8 * mC[j + 2];
            }
            if (!COMPACT_OUT) {
                float* orow = dst + (size_t)ro * out_pitch + XOFF;
                if (x0 + 3 < NI) {
                    float4 ov;
                    ov.x = o[0] + g4.x; ov.y = o[1] + g4.y;
                    ov.z = o[2] + g4.z; ov.w = o[3] + g4.w;
                    *(float4*)(orow + x0) = ov;
                } else {
                    if (x0 + 0 < NI) orow[x0 + 0] = o[0] + g4.x;
                    if (x0 + 1 < NI) orow[x0 + 1] = o[1] + g4.y;
                }
            } else {
                float* orow = dst + (size_t)ro * out_pitch;   // compact d_out
                if (x0 + 0 < NI) orow[x0 + 0] = o[0] + g4.x;
                if (x0 + 1 < NI) orow[x0 + 1] = o[1] + g4.y;
                if (x0 + 2 < NI) orow[x0 + 2] = o[2] + g4.z;
                if (x0 + 3 < NI) orow[x0 + 3] = o[3] + g4.w;
            }
        }
    }
}

extern "C" void kernel_launch(void* const* d_in, const int* in_sizes, int n_in,
                              void* d_out, int out_size) {
    // metadata order: x, pre, f, mu, k1, k2, k3  (x unused by the reference)
    const float* pre = (const float*)d_in[1];
    const float* f   = (const float*)d_in[2];
    const float* mu  = (const float*)d_in[3];
    const float* k1  = (const float*)d_in[4];
    const float* k2  = (const float*)d_in[5];
    const float* k3  = (const float*)d_in[6];
    float* out = (float*)d_out;

    void *pA = nullptr, *pB = nullptr, *pC = nullptr;
    cudaGetSymbolAddress(&pA, g_bufA);
    cudaGetSymbolAddress(&pB, g_bufB);
    cudaGetSymbolAddress(&pC, g_coef);

    setup_coef_kernel<<<1, 1>>>(mu, k1, k2, k3);
    cudaMemcpyToSymbolAsync(c_coef, pC, 9 * sizeof(float), 0,
                            cudaMemcpyDeviceToDevice);

    dim3 blk8(32, TY, 1);
    dim3 grd8(NF / 128, (NI + TY * ROWS - 1) / (TY * ROWS), BATCH);

    // G = force + conv(pad(force))
    gforce_kernel<<<grd8, blk8>>>(f);

    // step 0: pre,f -> bufA
    step0_kernel<<<grd8, blk8>>>(pre, f, (float*)pA);

    // 5 fused double-steps: steps 1..10
    dim3 fblk(32, FTY2, 1);
    dim3 fgrd(NF / 128, (NI + FTY2 * RROWS - 1) / (FTY2 * RROWS), BATCH);

    fused2r_kernel<false><<<fgrd, fblk>>>((const float*)pA, (float*)pB, PITCH);
    fused2r_kernel<false><<<fgrd, fblk>>>((const float*)pB, (float*)pA, PITCH);
    fused2r_kernel<false><<<fgrd, fblk>>>((const float*)pA, (float*)pB, PITCH);
    fused2r_kernel<false><<<fgrd, fblk>>>((const float*)pB, (float*)pA, PITCH);
    fused2r_kernel<true ><<<fgrd, fblk>>>((const float*)pA, out, NI);
}

// round 14
// speedup vs baseline: 1.2074x; 1.2074x over previous
#include <cuda_runtime.h>

#define NI      1022      // interior size (N-2)
#define NF      1024      // full size N
#define PITCH   1056      // padded row pitch (33*128B rows)
#define XOFF    16        // field starts at col 16 -> loads at x-4 stay in-bounds
#define BATCH   8
#define ROWS0   4         // output rows per thread (step-0G kernel)
#define TY      4         // thread rows per block (step-0G kernel)
#define RROWS   16        // output rows per thread (fused rolling kernel)
#define FTY2    4         // thread.y per block (fused rolling kernel)

// zero-initialized at context init; padding cols never written -> stay zero
__device__ float g_bufA[BATCH * NI * PITCH];
__device__ float g_bufB[BATCH * NI * PITCH];
__device__ float g_G[BATCH * NI * PITCH];     // G = force + conv(pad(force))
__device__ float g_coef[9];
__device__ float g_cf[1];

__constant__ float c_coef[9];

// --- fold mu/k1/k2/k3 into 10 scalars ---------------------------------------
__global__ void setup_coef_kernel(const float* __restrict__ mu,
                                  const float* __restrict__ k1,
                                  const float* __restrict__ k2,
                                  const float* __restrict__ k3) {
    float s3 = 0.0f;
    #pragma unroll
    for (int i = 0; i < 9; i++) s3 += k3[i];
    float inv = 1.0f / s3;
    #pragma unroll
    for (int i = 0; i < 9; i++) g_coef[i] = (k1[i] + k2[i]) * inv;
    const float Hval = 1.0f / (float)(NF - 1);
    g_cf[0] = Hval * Hval / (mu[0] * s3);
}

// --- step0G: one rolled pass computing BOTH outputs --------------------------
//   bufA = force + conv(pad(pre))      (the first Jacobi step)
//   g_G  = force + conv(pad(force))    (force term folded for later passes)
// with force = cf * f_interior. Reads pre and f exactly once per source row.
__global__ void __launch_bounds__(32 * TY)
step0G_kernel(const float* __restrict__ pre,
              const float* __restrict__ f,
              float* __restrict__ outA) {
    int lane  = threadIdx.x;
    int x0    = (blockIdx.x * 32 + lane) * 4;
    int ybase = (blockIdx.y * TY + threadIdx.y) * ROWS0;
    int b     = blockIdx.z;
    if (ybase >= NI) return;

    float c0 = c_coef[0], c1 = c_coef[1], c2 = c_coef[2];
    float c3 = c_coef[3], c4 = c_coef[4], c5 = c_coef[5];
    float c6 = c_coef[6], c7 = c_coef[7], c8 = c_coef[8];
    const float cf = g_cf[0];

    const float* srcP = pre + (size_t)b * NI * NI;

    float4 accP[ROWS0], accG[ROWS0];
    #pragma unroll
    for (int i = 0; i < ROWS0; i++) {
        accP[i].x = accP[i].y = accP[i].z = accP[i].w = 0.f;
        accG[i] = accP[i];
    }

    #pragma unroll
    for (int rj = 0; rj <= ROWS0 + 1; rj++) {
        int ri  = rj - 1;
        int row = ybase + ri;
        if (row < 0 || row >= NI) continue;

        // ---- pre window p[0..5] = pre[row][x0-1 .. x0+4] (zero-padded) ------
        const float* rp = srcP + (size_t)row * NI;
        float p[6];
        p[0] = (x0 - 1 >= 0 && x0 - 1 < NI) ? rp[x0 - 1] : 0.0f;
        p[1] = (x0 + 0 < NI) ? rp[x0 + 0] : 0.0f;
        p[2] = (x0 + 1 < NI) ? rp[x0 + 1] : 0.0f;
        p[3] = (x0 + 2 < NI) ? rp[x0 + 2] : 0.0f;
        p[4] = (x0 + 3 < NI) ? rp[x0 + 3] : 0.0f;
        p[5] = (x0 + 4 < NI) ? rp[x0 + 4] : 0.0f;

        // ---- force window w[0..5] = force[row][x0-1 .. x0+4] ----------------
        // force[row][c] = cf * f[row+1][c+1]; e[i] = f[row+1][x0+i]
        const float* fr = f + ((size_t)b * NF + (row + 1)) * NF;
        float4 qa = *(const float4*)(fr + x0);
        float e4 = 0.f, e5 = 0.f;
        if (x0 + 8 <= NF) {
            float4 qb = *(const float4*)(fr + x0 + 4);
            e4 = qb.x; e5 = qb.y;
        }
        float e[6] = { qa.x, qa.y, qa.z, qa.w, e4, e5 };
        float w[6];
        #pragma unroll
        for (int i = 0; i < 6; i++) {
            int cc = x0 - 1 + i;
            w[i] = ((unsigned)cc < (unsigned)NI) ? cf * e[i] : 0.f;
        }

        if (ri + 1 >= 0 && ri + 1 < ROWS0) {      // top taps -> output row ri+1
            accP[ri + 1].x += c0 * p[0] + c1 * p[1] + c2 * p[2];
            accP[ri + 1].y += c0 * p[1] + c1 * p[2] + c2 * p[3];
            accP[ri + 1].z += c0 * p[2] + c1 * p[3] + c2 * p[4];
            accP[ri + 1].w += c0 * p[3] + c1 * p[4] + c2 * p[5];
            accG[ri + 1].x += c0 * w[0] + c1 * w[1] + c2 * w[2];
            accG[ri + 1].y += c0 * w[1] + c1 * w[2] + c2 * w[3];
            accG[ri + 1].z += c0 * w[2] + c1 * w[3] + c2 * w[4];
            accG[ri + 1].w += c0 * w[3] + c1 * w[4] + c2 * w[5];
        }
        if (ri >= 0 && ri < ROWS0) {              // mid taps + center force
            accP[ri].x += c3 * p[0] + c4 * p[1] + c5 * p[2] + w[1];
            accP[ri].y += c3 * p[1] + c4 * p[2] + c5 * p[3] + w[2];
            accP[ri].z += c3 * p[2] + c4 * p[3] + c5 * p[4] + w[3];
            accP[ri].w += c3 * p[3] + c4 * p[4] + c5 * p[5] + w[4];
            accG[ri].x += c3 * w[0] + c4 * w[1] + c5 * w[2] + w[1];
            accG[ri].y += c3 * w[1] + c4 * w[2] + c5 * w[3] + w[2];
            accG[ri].z += c3 * w[2] + c4 * w[3] + c5 * w[4] + w[3];
            accG[ri].w += c3 * w[3] + c4 * w[4] + c5 * w[5] + w[4];
        }
        if (ri - 1 >= 0 && ri - 1 < ROWS0) {      // bottom taps -> row ri-1
            accP[ri - 1].x += c6 * p[0] + c7 * p[1] + c8 * p[2];
            accP[ri - 1].y += c6 * p[1] + c7 * p[2] + c8 * p[3];
            accP[ri - 1].z += c6 * p[2] + c7 * p[3] + c8 * p[4];
            accP[ri - 1].w += c6 * p[3] + c7 * p[4] + c8 * p[5];
            accG[ri - 1].x += c6 * w[0] + c7 * w[1] + c8 * w[2];
            accG[ri - 1].y += c6 * w[1] + c7 * w[2] + c8 * w[3];
            accG[ri - 1].z += c6 * w[2] + c7 * w[3] + c8 * w[4];
            accG[ri - 1].w += c6 * w[3] + c7 * w[4] + c8 * w[5];
        }
    }

    #pragma unroll
    for (int i = 0; i < ROWS0; i++) {
        int row = ybase + i;
        if (row >= NI) continue;
        float* arow = outA + ((size_t)b * NI + row) * PITCH + XOFF;
        float* grow = g_G  + ((size_t)b * NI + row) * PITCH + XOFF;
        if (x0 + 3 < NI) {
            *(float4*)(arow + x0) = accP[i];
            *(float4*)(grow + x0) = accG[i];
        } else {
            if (x0 + 0 < NI) { arow[x0 + 0] = accP[i].x; grow[x0 + 0] = accG[i].x; }
            if (x0 + 1 < NI) { arow[x0 + 1] = accP[i].y; grow[x0 + 1] = accG[i].y; }
        }
    }
}

// --- fused 2-step Jacobi: mid = conv(in); out = G + conv(mid) -----------------
// G prefetched one iteration ahead so its load latency is hidden.
template<bool COMPACT_OUT>
__global__ void __launch_bounds__(32 * FTY2)
fused2r_kernel(const float* __restrict__ in,
               float* __restrict__ out, int out_pitch) {
    const int lane  = threadIdx.x;
    const int x0    = (blockIdx.x * 32 + lane) * 4;
    const int ybase = (blockIdx.y * FTY2 + threadIdx.y) * RROWS;
    const int b     = blockIdx.z;

    const float c0 = c_coef[0], c1 = c_coef[1], c2 = c_coef[2];
    const float c3 = c_coef[3], c4 = c_coef[4], c5 = c_coef[5];
    const float c6 = c_coef[6], c7 = c_coef[7], c8 = c_coef[8];

    const float* src = in  + (size_t)b * NI * PITCH + XOFF;
    const float* gsc = g_G + (size_t)b * NI * PITCH + XOFF;
    float*       dst = out + (size_t)b * NI * out_pitch;

    float inA[8], inB[8], inC[8];   // input rows r-2, r-1, r (cols x0-2..x0+5)
    float mA[6],  mB[6],  mC[6];    // mid rows r-3, r-2, r-1 (cols x0-1..x0+4)
    float4 gNxt;                    // prefetched G row for next iter's output

    #pragma unroll
    for (int i = 0; i < 8; i++) { inA[i] = 0.f; inB[i] = 0.f; inC[i] = 0.f; }
    #pragma unroll
    for (int i = 0; i < 6; i++) { mA[i] = 0.f; mB[i] = 0.f; mC[i] = 0.f; }
    gNxt.x = gNxt.y = gNxt.z = gNxt.w = 0.f;

    const float* rp = src + (size_t)(ybase - 2) * PITCH;

    for (int it = 0; it < RROWS + 4; it++) {
        const int r = ybase - 2 + it;

        // ---- consume previous prefetch; issue next G prefetch (row r-1) -----
        float4 gCur = gNxt;                   // G[r-2] when valid
        const int rn = r - 1;                 // next iteration's output row
        if (rn >= ybase && rn < ybase + RROWS && rn < NI)
            gNxt = *(const float4*)(gsc + (size_t)rn * PITCH + x0);

        // ---- shift input window, load row r (3 aligned float4) ---------------
        #pragma unroll
        for (int i = 0; i < 8; i++) { inA[i] = inB[i]; inB[i] = inC[i]; }
        if ((unsigned)r < (unsigned)NI) {
            float4 qa = *(const float4*)(rp + x0 - 4);
            float4 qb = *(const float4*)(rp + x0);
            float4 qc = *(const float4*)(rp + x0 + 4);
            inC[0] = qa.z; inC[1] = qa.w;
            inC[2] = qb.x; inC[3] = qb.y; inC[4] = qb.z; inC[5] = qb.w;
            inC[6] = qc.x; inC[7] = qc.y;
        } else {
            #pragma unroll
            for (int i = 0; i < 8; i++) inC[i] = 0.f;
        }
        rp += PITCH;

        // ---- shift mid window, compute mid row rm = r-1 (pure conv) ----------
        #pragma unroll
        for (int i = 0; i < 6; i++) { mA[i] = mB[i]; mB[i] = mC[i]; }

        const int rm = r - 1;
        if ((unsigned)rm < (unsigned)NI) {
            #pragma unroll
            for (int i = 0; i < 6; i++) {
                int gc = x0 - 1 + i;
                float vmid =
                      c0 * inA[i] + c1 * inA[i + 1] + c2 * inA[i + 2]
                    + c3 * inB[i] + c4 * inB[i + 1] + c5 * inB[i + 2]
                    + c6 * inC[i] + c7 * inC[i + 1] + c8 * inC[i + 2];
                mC[i] = ((unsigned)gc < (unsigned)NI) ? vmid : 0.f;
            }
        } else {
            #pragma unroll
            for (int i = 0; i < 6; i++) mC[i] = 0.f;
        }

        // ---- output row ro = r-2: out = G + conv(mid) ------------------------
        const int ro = r - 2;
        if (ro >= ybase && ro < NI) {
            float o[4];
            #pragma unroll
            for (int j = 0; j < 4; j++) {
                o[j] = c0 * mA[j] + c1 * mA[j + 1] + c2 * mA[j + 2]
                     + c3 * mB[j] + c4 * mB[j + 1] + c5 * mB[j + 2]
                     + c6 * mC[j] + c7 * mC[j + 1] + c8 * mC[j + 2];
            }
            if (!COMPACT_OUT) {
                float* orow = dst + (size_t)ro * out_pitch + XOFF;
                if (x0 + 3 < NI) {
                    float4 ov;
                    ov.x = o[0] + gCur.x; ov.y = o[1] + gCur.y;
                    ov.z = o[2] + gCur.z; ov.w = o[3] + gCur.w;
                    *(float4*)(orow + x0) = ov;
                } else {
                    if (x0 + 0 < NI) orow[x0 + 0] = o[0] + gCur.x;
                    if (x0 + 1 < NI) orow[x0 + 1] = o[1] + gCur.y;
                }
            } else {
                float* orow = dst + (size_t)ro * out_pitch;   // compact d_out
                if (x0 + 0 < NI) orow[x0 + 0] = o[0] + gCur.x;
                if (x0 + 1 < NI) orow[x0 + 1] = o[1] + gCur.y;
                if (x0 + 2 < NI) orow[x0 + 2] = o[2] + gCur.z;
                if (x0 + 3 < NI) orow[x0 + 3] = o[3] + gCur.w;
            }
        }
    }
}

extern "C" void kernel_launch(void* const* d_in, const int* in_sizes, int n_in,
                              void* d_out, int out_size) {
    // metadata order: x, pre, f, mu, k1, k2, k3  (x unused by the reference)
    const float* pre = (const float*)d_in[1];
    const float* f   = (const float*)d_in[2];
    const float* mu  = (const float*)d_in[3];
    const float* k1  = (const float*)d_in[4];
    const float* k2  = (const float*)d_in[5];
    const float* k3  = (const float*)d_in[6];
    float* out = (float*)d_out;

    void *pA = nullptr, *pB = nullptr, *pC = nullptr;
    cudaGetSymbolAddress(&pA, g_bufA);
    cudaGetSymbolAddress(&pB, g_bufB);
    cudaGetSymbolAddress(&pC, g_coef);

    setup_coef_kernel<<<1, 1>>>(mu, k1, k2, k3);
    cudaMemcpyToSymbolAsync(c_coef, pC, 9 * sizeof(float), 0,
                            cudaMemcpyDeviceToDevice);

    // step 0 + G precompute in ONE pass: pre,f -> bufA, g_G
    {
        dim3 blk(32, TY, 1);
        dim3 grd(NF / 128, (NI + TY * ROWS0 - 1) / (TY * ROWS0), BATCH);
        step0G_kernel<<<grd, blk>>>(pre, f, (float*)pA);
    }

    // 5 fused double-steps: steps 1..10
    dim3 fblk(32, FTY2, 1);
    dim3 fgrd(NF / 128, (NI + FTY2 * RROWS - 1) / (FTY2 * RROWS), BATCH);

    fused2r_kernel<false><<<fgrd, fblk>>>((const float*)pA, (float*)pB, PITCH);
    fused2r_kernel<false><<<fgrd, fblk>>>((const float*)pB, (float*)pA, PITCH);
    fused2r_kernel<false><<<fgrd, fblk>>>((const float*)pA, (float*)pB, PITCH);
    fused2r_kernel<false><<<fgrd, fblk>>>((const float*)pB, (float*)pA, PITCH);
    fused2r_kernel<true ><<<fgrd, fblk>>>((const float*)pA, out, NI);
}